// round 1
// baseline (speedup 1.0000x reference)
#include <cuda_runtime.h>
#include <cstdint>

// Problem shapes (fixed by the dataset: q/k (4,16,4096,64) f32, cos/sin (4,4096,64), vs (32,64))
#define DD 64
#define BB 4
#define HHH 16
#define SSS 4096
#define NROWS_Q (BB*HHH*SSS)   // 262144
#define NROWS_T (2*NROWS_Q)    // 524288
#define NREFL 32
#define TPB 128

__device__ float g_Q[DD*DD];   // Q[i][j], row-major
__device__ float g_QT[DD*DD];  // QT[j][i] = Q[i][j]

// ---------------- packed f32x2 helpers (Blackwell FFMA2 path) ----------------
__device__ __forceinline__ unsigned long long pk2(float lo, float hi) {
    unsigned long long r;
    asm("mov.b64 %0, {%1, %2};" : "=l"(r) : "f"(lo), "f"(hi));
    return r;
}
__device__ __forceinline__ void upk2(unsigned long long v, float& lo, float& hi) {
    asm("mov.b64 {%0, %1}, %2;" : "=f"(lo), "=f"(hi) : "l"(v));
}
__device__ __forceinline__ unsigned long long ffma2(unsigned long long a,
                                                    unsigned long long b,
                                                    unsigned long long c) {
    unsigned long long d;
    asm("fma.rn.f32x2 %0, %1, %2, %3;" : "=l"(d) : "l"(a), "l"(b), "l"(c));
    return d;
}
__device__ __forceinline__ unsigned long long fmul2(unsigned long long a,
                                                    unsigned long long b) {
    unsigned long long d;
    asm("mul.rn.f32x2 %0, %1, %2;" : "=l"(d) : "l"(a), "l"(b));
    return d;
}

// ---------------- Kernel A: build Q from 32 sequential Householder reflections ----------------
// Replicates: Q0 = I; Q <- Q - (2/(v.v+1e-8)) * outer(v, v @ Q), for vs[0..31] in order.
// One block, 256 threads: thread (j = t&63, p = t>>6) owns rows [16p,16p+16) of column j.
__global__ void build_q_kernel(const float* __restrict__ vs) {
    __shared__ float Qs[DD*DD];
    __shared__ float vsh[DD];
    __shared__ float wpart[4][DD];
    __shared__ float coefs[NREFL];
    const int t = threadIdx.x;
    const int j = t & 63;
    const int p = t >> 6;

    // Q = I
    for (int i = p*16; i < p*16 + 16; ++i)
        Qs[i*DD + j] = (i == j) ? 1.0f : 0.0f;

    // precompute coef_r = 2 / (||v_r||^2 + 1e-8)
    if (t < NREFL) {
        float s = 0.0f;
        for (int c = 0; c < DD; ++c) { float v = vs[t*DD + c]; s += v*v; }
        coefs[t] = 2.0f / (s + 1e-8f);
    }
    __syncthreads();

    for (int r = 0; r < NREFL; ++r) {
        if (t < DD) vsh[t] = vs[r*DD + t];
        __syncthreads();
        // w_j = sum_i v_i * Q[i][j]  (partial over this thread's 16 rows)
        float w = 0.0f;
        #pragma unroll
        for (int i = 0; i < 16; ++i) {
            int ii = p*16 + i;
            w += vsh[ii] * Qs[ii*DD + j];
        }
        wpart[p][j] = w;
        __syncthreads();
        float wj = wpart[0][j] + wpart[1][j] + wpart[2][j] + wpart[3][j];
        float cw = coefs[r] * wj;
        #pragma unroll
        for (int i = 0; i < 16; ++i) {
            int ii = p*16 + i;
            Qs[ii*DD + j] -= vsh[ii] * cw;
        }
        __syncthreads();
    }

    // write Q and its transpose to global
    for (int idx = t; idx < DD*DD; idx += blockDim.x) {
        float v = Qs[idx];
        int i = idx >> 6, jj = idx & 63;
        g_Q[idx] = v;
        g_QT[jj*DD + i] = v;
    }
}

// ---------------- Kernel B: out = Q^T * rope(Q * x) per row ----------------
// One thread per row. Q / QT staged in shared (broadcast LDS.128).
// All math in packed f32x2.
__global__ void __launch_bounds__(TPB) rnrope_kernel(
    const float* __restrict__ qin, const float* __restrict__ kin,
    const float* __restrict__ cosp, const float* __restrict__ sinp,
    float* __restrict__ out)
{
    __shared__ __align__(16) float sQ[DD*DD];   // Q[i][j]  (GEMM2: out pairs contiguous in j)
    __shared__ __align__(16) float sQT[DD*DD];  // QT[j][i] (GEMM1: y pairs contiguous in i)
    const int tid = threadIdx.x;
    #pragma unroll 4
    for (int idx = tid; idx < DD*DD; idx += TPB) {
        sQ[idx]  = g_Q[idx];
        sQT[idx] = g_QT[idx];
    }
    __syncthreads();

    const long long row = (long long)blockIdx.x * TPB + tid;   // grid covers exactly NROWS_T
    const float* src;
    long long r;
    if (row < NROWS_Q) { src = qin; r = row; }
    else               { src = kin; r = row - NROWS_Q; }

    // r = ((b*H + h)*S + s); H*S = 65536, S = 4096
    const int b = (int)(r >> 16);
    const int s = (int)(r & (SSS - 1));
    const size_t coff = ((size_t)b * SSS + (size_t)s) * DD;

    // ---- load x row (64 floats) ----
    const float4* x4 = (const float4*)(src + r * DD);
    float x[DD];
    #pragma unroll
    for (int t4 = 0; t4 < 16; ++t4) {
        float4 v = x4[t4];
        x[4*t4+0] = v.x; x[4*t4+1] = v.y; x[4*t4+2] = v.z; x[4*t4+3] = v.w;
    }

    // ---- GEMM1: y_i = sum_j Q[i][j] * x[j]; pairs along i via sQT rows ----
    unsigned long long y2[32];
    {
        unsigned long long xx = pk2(x[0], x[0]);
        const ulonglong2* qt = (const ulonglong2*)(sQT);
        #pragma unroll
        for (int i4 = 0; i4 < 16; ++i4) {
            ulonglong2 qq = qt[i4];
            y2[2*i4]   = fmul2(qq.x, xx);
            y2[2*i4+1] = fmul2(qq.y, xx);
        }
    }
    #pragma unroll
    for (int j = 1; j < DD; ++j) {
        unsigned long long xx = pk2(x[j], x[j]);
        const ulonglong2* qt = (const ulonglong2*)(sQT + j*DD);
        #pragma unroll
        for (int i4 = 0; i4 < 16; ++i4) {
            ulonglong2 qq = qt[i4];
            y2[2*i4]   = ffma2(qq.x, xx, y2[2*i4]);
            y2[2*i4+1] = ffma2(qq.y, xx, y2[2*i4+1]);
        }
    }

    // ---- rope: z_i = y_i*cos_i + rot(y)_i*sin_i ----
    // rot(y)_i = -y[i+32] for i<32, y[i-32] for i>=32
    const ulonglong2* c2 = (const ulonglong2*)(cosp + coff);
    const ulonglong2* s2 = (const ulonglong2*)(sinp + coff);
    const unsigned long long SGN = 0x8000000080000000ULL;
    unsigned long long z2[32];
    #pragma unroll
    for (int g = 0; g < 8; ++g) {       // i in [4g, 4g+3], low half (i < 32)
        ulonglong2 cc = c2[g];
        ulonglong2 ss = s2[g];
        unsigned long long ns0 = ss.x ^ SGN;
        unsigned long long ns1 = ss.y ^ SGN;
        z2[2*g]   = ffma2(y2[2*g],   cc.x, fmul2(y2[2*g+16], ns0));
        z2[2*g+1] = ffma2(y2[2*g+1], cc.y, fmul2(y2[2*g+17], ns1));
    }
    #pragma unroll
    for (int g = 8; g < 16; ++g) {      // high half (i >= 32): + y[i-32]*sin
        ulonglong2 cc = c2[g];
        ulonglong2 ss = s2[g];
        z2[2*g]   = ffma2(y2[2*g],   cc.x, fmul2(y2[2*g-16], ss.x));
        z2[2*g+1] = ffma2(y2[2*g+1], cc.y, fmul2(y2[2*g-15], ss.y));
    }

    // ---- GEMM2: out_j = sum_i Q[i][j] * z_i; pairs along j via sQ rows ----
    unsigned long long o2[32];
    {
        float zlo, zhi; upk2(z2[0], zlo, zhi);
        unsigned long long zz0 = pk2(zlo, zlo);
        unsigned long long zz1 = pk2(zhi, zhi);
        const ulonglong2* qr0 = (const ulonglong2*)(sQ);
        const ulonglong2* qr1 = (const ulonglong2*)(sQ + DD);
        #pragma unroll
        for (int j4 = 0; j4 < 16; ++j4) {
            ulonglong2 qq = qr0[j4];
            o2[2*j4]   = fmul2(qq.x, zz0);
            o2[2*j4+1] = fmul2(qq.y, zz0);
        }
        #pragma unroll
        for (int j4 = 0; j4 < 16; ++j4) {
            ulonglong2 qq = qr1[j4];
            o2[2*j4]   = ffma2(qq.x, zz1, o2[2*j4]);
            o2[2*j4+1] = ffma2(qq.y, zz1, o2[2*j4+1]);
        }
    }
    #pragma unroll
    for (int i2 = 1; i2 < 32; ++i2) {
        float zlo, zhi; upk2(z2[i2], zlo, zhi);
        unsigned long long zz0 = pk2(zlo, zlo);
        unsigned long long zz1 = pk2(zhi, zhi);
        const ulonglong2* qr0 = (const ulonglong2*)(sQ + (2*i2)*DD);
        const ulonglong2* qr1 = (const ulonglong2*)(sQ + (2*i2+1)*DD);
        #pragma unroll
        for (int j4 = 0; j4 < 16; ++j4) {
            ulonglong2 qq = qr0[j4];
            o2[2*j4]   = ffma2(qq.x, zz0, o2[2*j4]);
            o2[2*j4+1] = ffma2(qq.y, zz0, o2[2*j4+1]);
        }
        #pragma unroll
        for (int j4 = 0; j4 < 16; ++j4) {
            ulonglong2 qq = qr1[j4];
            o2[2*j4]   = ffma2(qq.x, zz1, o2[2*j4]);
            o2[2*j4+1] = ffma2(qq.y, zz1, o2[2*j4+1]);
        }
    }

    // ---- store (out layout: [q_out (NROWS_Q rows) | k_out (NROWS_Q rows)]) ----
    ulonglong2* d4 = (ulonglong2*)(out + row * DD);
    #pragma unroll
    for (int t4 = 0; t4 < 16; ++t4) {
        ulonglong2 vv;
        vv.x = o2[2*t4];
        vv.y = o2[2*t4+1];
        d4[t4] = vv;
    }
}

extern "C" void kernel_launch(void* const* d_in, const int* in_sizes, int n_in,
                              void* d_out, int out_size) {
    const float* q    = (const float*)d_in[0];
    const float* k    = (const float*)d_in[1];
    const float* cosp = (const float*)d_in[2];
    const float* sinp = (const float*)d_in[3];
    const float* vs   = (const float*)d_in[4];
    float* out = (float*)d_out;

    build_q_kernel<<<1, 256>>>(vs);
    rnrope_kernel<<<NROWS_T / TPB, TPB>>>(q, k, cosp, sinp, out);
}

// round 2
// speedup vs baseline: 2.8583x; 2.8583x over previous
#include <cuda_runtime.h>
#include <cuda_bf16.h>
#include <cstdint>

// Shapes fixed by dataset: q/k (4,16,4096,64) f32, cos/sin (4,4096,64) f32, vs (32,64) f32
#define DD 64
#define SSS 4096
#define NROWS_Q (4*16*4096)    // 262144
#define NROWS_T (2*NROWS_Q)    // 524288
#define NREFL 32

// mma-ready packed bf16 B fragments, [ (kt*8+nt)*32 + lane ] -> uint2{b0,b1}
// GEMM1: B1[k=j][n=i] = Q[i][j]   (Y = X * Q^T)
// GEMM2: B2[k=i][n=j] = Q[i][j]   (O = Z * Q)
__device__ uint2 g_B1hi[1024];
__device__ uint2 g_B1lo[1024];
__device__ uint2 g_B2hi[1024];
__device__ uint2 g_B2lo[1024];

// ---------------- Kernel A: build Q (Householder scan) + pack mma fragments ----------------
__global__ void build_q_kernel(const float* __restrict__ vs) {
    __shared__ float Qs[DD*DD];
    __shared__ float vsh[DD];
    __shared__ float wpart[4][DD];
    __shared__ float coefs[NREFL];
    const int t = threadIdx.x;          // 256 threads
    const int j = t & 63;
    const int p = t >> 6;

    for (int i = p*16; i < p*16 + 16; ++i)
        Qs[i*DD + j] = (i == j) ? 1.0f : 0.0f;

    if (t < NREFL) {
        float s = 0.0f;
        for (int c = 0; c < DD; ++c) { float v = vs[t*DD + c]; s += v*v; }
        coefs[t] = 2.0f / (s + 1e-8f);
    }
    __syncthreads();

    for (int r = 0; r < NREFL; ++r) {
        if (t < DD) vsh[t] = vs[r*DD + t];
        __syncthreads();
        float w = 0.0f;
        #pragma unroll
        for (int i = 0; i < 16; ++i) {
            int ii = p*16 + i;
            w += vsh[ii] * Qs[ii*DD + j];
        }
        wpart[p][j] = w;
        __syncthreads();
        float wj = wpart[0][j] + wpart[1][j] + wpart[2][j] + wpart[3][j];
        float cw = coefs[r] * wj;
        #pragma unroll
        for (int i = 0; i < 16; ++i) {
            int ii = p*16 + i;
            Qs[ii*DD + j] -= vsh[ii] * cw;
        }
        __syncthreads();
    }

    // pack B fragments (hi/lo bf16 split) for both GEMMs
    for (int slot = t; slot < 1024; slot += 256) {
        int lane = slot & 31, frag = slot >> 5;
        int kt = frag >> 3, nt = frag & 7;
        int g = lane >> 2, t4 = lane & 3;
        int n  = 8*nt + g;
        int k0 = 16*kt + 2*t4;

        // ---- B1 (element at (k,n) = Q[n][k]) ----
        {
            float e0 = Qs[n*DD + k0],     e1 = Qs[n*DD + k0 + 1];
            float e2 = Qs[n*DD + k0 + 8], e3 = Qs[n*DD + k0 + 9];
            __nv_bfloat162 h0 = __floats2bfloat162_rn(e0, e1);
            __nv_bfloat162 h1 = __floats2bfloat162_rn(e2, e3);
            float r0 = e0 - __bfloat162float(h0.x), r1 = e1 - __bfloat162float(h0.y);
            float r2 = e2 - __bfloat162float(h1.x), r3 = e3 - __bfloat162float(h1.y);
            __nv_bfloat162 l0 = __floats2bfloat162_rn(r0, r1);
            __nv_bfloat162 l1 = __floats2bfloat162_rn(r2, r3);
            g_B1hi[slot] = make_uint2(*(uint32_t*)&h0, *(uint32_t*)&h1);
            g_B1lo[slot] = make_uint2(*(uint32_t*)&l0, *(uint32_t*)&l1);
        }
        // ---- B2 (element at (k,n) = Q[k][n]) ----
        {
            float e0 = Qs[k0*DD + n],     e1 = Qs[(k0+1)*DD + n];
            float e2 = Qs[(k0+8)*DD + n], e3 = Qs[(k0+9)*DD + n];
            __nv_bfloat162 h0 = __floats2bfloat162_rn(e0, e1);
            __nv_bfloat162 h1 = __floats2bfloat162_rn(e2, e3);
            float r0 = e0 - __bfloat162float(h0.x), r1 = e1 - __bfloat162float(h0.y);
            float r2 = e2 - __bfloat162float(h1.x), r3 = e3 - __bfloat162float(h1.y);
            __nv_bfloat162 l0 = __floats2bfloat162_rn(r0, r1);
            __nv_bfloat162 l1 = __floats2bfloat162_rn(r2, r3);
            g_B2hi[slot] = make_uint2(*(uint32_t*)&h0, *(uint32_t*)&h1);
            g_B2lo[slot] = make_uint2(*(uint32_t*)&l0, *(uint32_t*)&l1);
        }
    }
}

// ---------------- main kernel helpers ----------------
__device__ __forceinline__ uint32_t pk_bf16x2(float lo, float hi) {
    // pack: low 16 bits = bf16(lo), high 16 bits = bf16(hi)
    uint32_t d;
    asm("cvt.rn.bf16x2.f32 %0, %1, %2;" : "=r"(d) : "f"(hi), "f"(lo));
    return d;
}
__device__ __forceinline__ void split_bf16x2(float a, float b, uint32_t& hi, uint32_t& lo) {
    hi = pk_bf16x2(a, b);
    float ha = __uint_as_float(hi << 16);
    float hb = __uint_as_float(hi & 0xFFFF0000u);
    lo = pk_bf16x2(a - ha, b - hb);
}

#define MMA_BF16(c, a0, a1, a2, a3, b0, b1)                                        \
    asm volatile("mma.sync.aligned.m16n8k16.row.col.f32.bf16.bf16.f32 "            \
                 "{%0,%1,%2,%3}, {%4,%5,%6,%7}, {%8,%9}, {%0,%1,%2,%3};"           \
                 : "+f"(c[0]), "+f"(c[1]), "+f"(c[2]), "+f"(c[3])                   \
                 : "r"(a0), "r"(a1), "r"(a2), "r"(a3), "r"(b0), "r"(b1))

// ---------------- Kernel B: per-warp 16-row tile, two chained bf16 3-term GEMMs ----------------
__global__ void __launch_bounds__(256) rnrope_mma_kernel(
    const float* __restrict__ qin, const float* __restrict__ kin,
    const float* __restrict__ cosp, const float* __restrict__ sinp,
    float* __restrict__ out)
{
    const int tid  = threadIdx.x;
    const int warp = tid >> 5;
    const int lane = tid & 31;
    const int g    = lane >> 2;
    const int t4   = lane & 3;

    const long long tilebase = (long long)blockIdx.x * 128 + warp * 16;  // global row of tile start
    const float* src;
    long long rq;
    if (tilebase < NROWS_Q) { src = qin; rq = tilebase; }
    else                    { src = kin; rq = tilebase - NROWS_Q; }

    // rows of this thread within tile: r0 = base+g, r1 = base+g+8 (same b,h for all 16 rows)
    const int b = (int)(rq >> 16);                 // H*S = 65536
    const int s = (int)(rq & (SSS - 1));
    const size_t coff = ((size_t)b * SSS + (size_t)s) * DD;

    const float* x0p = src + (rq + g) * DD;
    const float* x1p = x0p + 8 * DD;

    // ---- load X rows, build A fragments (hi/lo bf16) ----
    uint32_t Ahi[4][4], Alo[4][4];
    #pragma unroll
    for (int kt = 0; kt < 4; ++kt) {
        int c0 = kt*16 + 2*t4;
        float2 p00 = *(const float2*)(x0p + c0);
        float2 p01 = *(const float2*)(x0p + c0 + 8);
        float2 p10 = *(const float2*)(x1p + c0);
        float2 p11 = *(const float2*)(x1p + c0 + 8);
        split_bf16x2(p00.x, p00.y, Ahi[kt][0], Alo[kt][0]);
        split_bf16x2(p10.x, p10.y, Ahi[kt][1], Alo[kt][1]);
        split_bf16x2(p01.x, p01.y, Ahi[kt][2], Alo[kt][2]);
        split_bf16x2(p11.x, p11.y, Ahi[kt][3], Alo[kt][3]);
    }

    // ---- GEMM1: Y = X * Q^T  (3-term bf16 split) ----
    float C[8][4];
    #pragma unroll
    for (int nt = 0; nt < 8; ++nt)
        #pragma unroll
        for (int e = 0; e < 4; ++e) C[nt][e] = 0.0f;

    #pragma unroll
    for (int nt = 0; nt < 8; ++nt) {
        #pragma unroll
        for (int kt = 0; kt < 4; ++kt) {
            uint2 bh = g_B1hi[(kt*8 + nt)*32 + lane];
            uint2 bl = g_B1lo[(kt*8 + nt)*32 + lane];
            MMA_BF16(C[nt], Ahi[kt][0], Ahi[kt][1], Ahi[kt][2], Ahi[kt][3], bh.x, bh.y);
            MMA_BF16(C[nt], Alo[kt][0], Alo[kt][1], Alo[kt][2], Alo[kt][3], bh.x, bh.y);
            MMA_BF16(C[nt], Ahi[kt][0], Ahi[kt][1], Ahi[kt][2], Ahi[kt][3], bl.x, bl.y);
        }
    }

    // ---- rope: z = y*cos + rot_half(y)*sin; pairing tile nt <-> nt+4 ----
    const float* cr0 = cosp + coff + (size_t)g * DD;
    const float* cr1 = cr0 + 8 * DD;
    const float* sr0 = sinp + coff + (size_t)g * DD;
    const float* sr1 = sr0 + 8 * DD;
    #pragma unroll
    for (int nt = 0; nt < 4; ++nt) {
        int c = 8*nt + 2*t4;
        float2 cl0 = *(const float2*)(cr0 + c);
        float2 cl1 = *(const float2*)(cr1 + c);
        float2 sl0 = *(const float2*)(sr0 + c);
        float2 sl1 = *(const float2*)(sr1 + c);
        float2 ch0 = *(const float2*)(cr0 + c + 32);
        float2 ch1 = *(const float2*)(cr1 + c + 32);
        float2 sh0 = *(const float2*)(sr0 + c + 32);
        float2 sh1 = *(const float2*)(sr1 + c + 32);

        float ylo, yhi;
        ylo = C[nt][0]; yhi = C[nt+4][0];
        C[nt][0]   = ylo*cl0.x - yhi*sl0.x;
        C[nt+4][0] = yhi*ch0.x + ylo*sh0.x;
        ylo = C[nt][1]; yhi = C[nt+4][1];
        C[nt][1]   = ylo*cl0.y - yhi*sl0.y;
        C[nt+4][1] = yhi*ch0.y + ylo*sh0.y;
        ylo = C[nt][2]; yhi = C[nt+4][2];
        C[nt][2]   = ylo*cl1.x - yhi*sl1.x;
        C[nt+4][2] = yhi*ch1.x + ylo*sh1.x;
        ylo = C[nt][3]; yhi = C[nt+4][3];
        C[nt][3]   = ylo*cl1.y - yhi*sl1.y;
        C[nt+4][3] = yhi*ch1.y + ylo*sh1.y;
    }

    // ---- Z (C fragments) -> A fragments of GEMM2 (hi/lo split) ----
    #pragma unroll
    for (int kt = 0; kt < 4; ++kt) {
        split_bf16x2(C[2*kt][0],   C[2*kt][1],   Ahi[kt][0], Alo[kt][0]);
        split_bf16x2(C[2*kt][2],   C[2*kt][3],   Ahi[kt][1], Alo[kt][1]);
        split_bf16x2(C[2*kt+1][0], C[2*kt+1][1], Ahi[kt][2], Alo[kt][2]);
        split_bf16x2(C[2*kt+1][2], C[2*kt+1][3], Ahi[kt][3], Alo[kt][3]);
    }

    // ---- GEMM2: O = Z * Q ----
    #pragma unroll
    for (int nt = 0; nt < 8; ++nt)
        #pragma unroll
        for (int e = 0; e < 4; ++e) C[nt][e] = 0.0f;

    #pragma unroll
    for (int nt = 0; nt < 8; ++nt) {
        #pragma unroll
        for (int kt = 0; kt < 4; ++kt) {
            uint2 bh = g_B2hi[(kt*8 + nt)*32 + lane];
            uint2 bl = g_B2lo[(kt*8 + nt)*32 + lane];
            MMA_BF16(C[nt], Ahi[kt][0], Ahi[kt][1], Ahi[kt][2], Ahi[kt][3], bh.x, bh.y);
            MMA_BF16(C[nt], Alo[kt][0], Alo[kt][1], Alo[kt][2], Alo[kt][3], bh.x, bh.y);
            MMA_BF16(C[nt], Ahi[kt][0], Ahi[kt][1], Ahi[kt][2], Ahi[kt][3], bl.x, bl.y);
        }
    }

    // ---- store O ----
    float* o0 = out + (tilebase + g) * DD;
    float* o1 = o0 + 8 * DD;
    #pragma unroll
    for (int nt = 0; nt < 8; ++nt) {
        int c = 8*nt + 2*t4;
        float2 v0; v0.x = C[nt][0]; v0.y = C[nt][1];
        float2 v1; v1.x = C[nt][2]; v1.y = C[nt][3];
        *(float2*)(o0 + c) = v0;
        *(float2*)(o1 + c) = v1;
    }
}

extern "C" void kernel_launch(void* const* d_in, const int* in_sizes, int n_in,
                              void* d_out, int out_size) {
    const float* q    = (const float*)d_in[0];
    const float* k    = (const float*)d_in[1];
    const float* cosp = (const float*)d_in[2];
    const float* sinp = (const float*)d_in[3];
    const float* vs   = (const float*)d_in[4];
    float* out = (float*)d_out;

    build_q_kernel<<<1, 256>>>(vs);
    rnrope_mma_kernel<<<NROWS_T / 128, 256>>>(q, k, cosp, sinp, out);
}

// round 3
// speedup vs baseline: 3.3841x; 1.1840x over previous
#include <cuda_runtime.h>
#include <cuda_bf16.h>
#include <cstdint>

// Shapes fixed by dataset: q/k (4,16,4096,64) f32, cos/sin (4,4096,64) f32, vs (32,64) f32
#define DD 64
#define SSS 4096
#define NROWS_Q (4*16*4096)    // 262144
#define NROWS_T (2*NROWS_Q)    // 524288
#define NREFL 32

// mma-ready packed bf16 B fragments, uint4 = {hi0, hi1, lo0, lo1}
// GEMM1: B1[k=j][n=i] = Q[i][j]   (Y = X * Q^T)
// GEMM2: B2[k=i][n=j] = Q[i][j]   (O = Z * Q)
__device__ uint4 g_B1[1024];
__device__ uint4 g_B2[1024];

// ---------------- Kernel A: build Q (Householder scan) + pack mma fragments ----------------
__global__ void build_q_kernel(const float* __restrict__ vs) {
    __shared__ float Qs[DD*DD];
    __shared__ float vsh[DD];
    __shared__ float wpart[4][DD];
    __shared__ float coefs[NREFL];
    const int t = threadIdx.x;          // 256 threads
    const int j = t & 63;
    const int p = t >> 6;

    for (int i = p*16; i < p*16 + 16; ++i)
        Qs[i*DD + j] = (i == j) ? 1.0f : 0.0f;

    if (t < NREFL) {
        float s = 0.0f;
        for (int c = 0; c < DD; ++c) { float v = vs[t*DD + c]; s += v*v; }
        coefs[t] = 2.0f / (s + 1e-8f);
    }
    __syncthreads();

    for (int r = 0; r < NREFL; ++r) {
        if (t < DD) vsh[t] = vs[r*DD + t];
        __syncthreads();
        float w = 0.0f;
        #pragma unroll
        for (int i = 0; i < 16; ++i) {
            int ii = p*16 + i;
            w += vsh[ii] * Qs[ii*DD + j];
        }
        wpart[p][j] = w;
        __syncthreads();
        float wj = wpart[0][j] + wpart[1][j] + wpart[2][j] + wpart[3][j];
        float cw = coefs[r] * wj;
        #pragma unroll
        for (int i = 0; i < 16; ++i) {
            int ii = p*16 + i;
            Qs[ii*DD + j] -= vsh[ii] * cw;
        }
        __syncthreads();
    }

    // pack B fragments (hi/lo bf16 split, uint4) for both GEMMs
    for (int slot = t; slot < 1024; slot += 256) {
        int lane = slot & 31, frag = slot >> 5;
        int kt = frag >> 3, nt = frag & 7;
        int g = lane >> 2, t4 = lane & 3;
        int n  = 8*nt + g;
        int k0 = 16*kt + 2*t4;

        // ---- B1 (element at (k,n) = Q[n][k]) ----
        {
            float e0 = Qs[n*DD + k0],     e1 = Qs[n*DD + k0 + 1];
            float e2 = Qs[n*DD + k0 + 8], e3 = Qs[n*DD + k0 + 9];
            __nv_bfloat162 h0 = __floats2bfloat162_rn(e0, e1);
            __nv_bfloat162 h1 = __floats2bfloat162_rn(e2, e3);
            float r0 = e0 - __bfloat162float(h0.x), r1 = e1 - __bfloat162float(h0.y);
            float r2 = e2 - __bfloat162float(h1.x), r3 = e3 - __bfloat162float(h1.y);
            __nv_bfloat162 l0 = __floats2bfloat162_rn(r0, r1);
            __nv_bfloat162 l1 = __floats2bfloat162_rn(r2, r3);
            g_B1[slot] = make_uint4(*(uint32_t*)&h0, *(uint32_t*)&h1,
                                    *(uint32_t*)&l0, *(uint32_t*)&l1);
        }
        // ---- B2 (element at (k,n) = Q[k][n]) ----
        {
            float e0 = Qs[k0*DD + n],     e1 = Qs[(k0+1)*DD + n];
            float e2 = Qs[(k0+8)*DD + n], e3 = Qs[(k0+9)*DD + n];
            __nv_bfloat162 h0 = __floats2bfloat162_rn(e0, e1);
            __nv_bfloat162 h1 = __floats2bfloat162_rn(e2, e3);
            float r0 = e0 - __bfloat162float(h0.x), r1 = e1 - __bfloat162float(h0.y);
            float r2 = e2 - __bfloat162float(h1.x), r3 = e3 - __bfloat162float(h1.y);
            __nv_bfloat162 l0 = __floats2bfloat162_rn(r0, r1);
            __nv_bfloat162 l1 = __floats2bfloat162_rn(r2, r3);
            g_B2[slot] = make_uint4(*(uint32_t*)&h0, *(uint32_t*)&h1,
                                    *(uint32_t*)&l0, *(uint32_t*)&l1);
        }
    }
}

// ---------------- helpers ----------------
__device__ __forceinline__ uint32_t pk_bf16x2(float lo, float hi) {
    uint32_t d;
    asm("cvt.rn.bf16x2.f32 %0, %1, %2;" : "=r"(d) : "f"(hi), "f"(lo));
    return d;
}
__device__ __forceinline__ void split_bf16x2(float a, float b, uint32_t& hi, uint32_t& lo) {
    hi = pk_bf16x2(a, b);
    float ha = __uint_as_float(hi << 16);
    float hb = __uint_as_float(hi & 0xFFFF0000u);
    lo = pk_bf16x2(a - ha, b - hb);
}

#define MMA_BF16(c, a0, a1, a2, a3, b0, b1)                                        \
    asm volatile("mma.sync.aligned.m16n8k16.row.col.f32.bf16.bf16.f32 "            \
                 "{%0,%1,%2,%3}, {%4,%5,%6,%7}, {%8,%9}, {%0,%1,%2,%3};"           \
                 : "+f"(c[0]), "+f"(c[1]), "+f"(c[2]), "+f"(c[3])                   \
                 : "r"(a0), "r"(a1), "r"(a2), "r"(a3), "r"(b0), "r"(b1))

// ---------------- Kernel B ----------------
// Block = 128 threads (4 warps). Block covers ONE (tensor, b, s-chunk of 8) across ALL 16 heads:
// 128 rows, local row rl = h*8 + ds. Each warp handles 2 M-tiles (32 rows).
// cos/sin tile is only 8 rows (shared by all heads & both fragment row-halves).
#define XS_STRIDE 68
__global__ void __launch_bounds__(128) rnrope_mma_kernel(
    const float* __restrict__ qin, const float* __restrict__ kin,
    const float* __restrict__ cosp, const float* __restrict__ sinp,
    float* __restrict__ out)
{
    __shared__ float xs[128 * XS_STRIDE];   // x tile; reused for out tile
    __shared__ float cs[8 * XS_STRIDE];
    __shared__ float ss[8 * XS_STRIDE];

    const int tid  = threadIdx.x;
    const int warp = tid >> 5;
    const int lane = tid & 31;
    const int g    = lane >> 2;
    const int t4   = lane & 3;

    const int bid    = blockIdx.x;          // 4096 blocks
    const int tensor = bid >> 11;           // 0 = q, 1 = k
    const int b      = (bid >> 9) & 3;
    const int s0     = (bid & 511) << 3;
    const float* src = tensor ? kin : qin;

    // ---- stage cos/sin (8 rows x 64) ----
    {
        int r  = tid >> 4;
        int c4 = (tid & 15) << 2;
        size_t gofs = ((size_t)(b * SSS + s0 + r)) * DD + c4;
        *(float4*)&cs[r * XS_STRIDE + c4] = *(const float4*)(cosp + gofs);
        *(float4*)&ss[r * XS_STRIDE + c4] = *(const float4*)(sinp + gofs);
    }
    // ---- stage x (128 rows x 64), coalesced per 8-row head chunk ----
    #pragma unroll
    for (int it = 0; it < 16; ++it) {
        int lin = it * 128 + tid;
        int rl  = lin >> 4;
        int c4  = (lin & 15) << 2;
        int h   = rl >> 3, ds = rl & 7;
        size_t gofs = (((size_t)(b * 16 + h)) * SSS + s0 + ds) * DD + c4;
        *(float4*)&xs[rl * XS_STRIDE + c4] = *(const float4*)(src + gofs);
    }
    __syncthreads();

    // ---- A1 fragments for the warp's two tiles ----
    uint32_t Ahi[2][4][4], Alo[2][4][4];
    #pragma unroll
    for (int tt = 0; tt < 2; ++tt) {
        int tb = (warp * 2 + tt) * 16;
        const float* x0 = &xs[(tb + g) * XS_STRIDE];
        const float* x1 = &xs[(tb + g + 8) * XS_STRIDE];
        #pragma unroll
        for (int kt = 0; kt < 4; ++kt) {
            int c0 = kt * 16 + 2 * t4;
            float2 p00 = *(const float2*)(x0 + c0);
            float2 p01 = *(const float2*)(x0 + c0 + 8);
            float2 p10 = *(const float2*)(x1 + c0);
            float2 p11 = *(const float2*)(x1 + c0 + 8);
            split_bf16x2(p00.x, p00.y, Ahi[tt][kt][0], Alo[tt][kt][0]);
            split_bf16x2(p10.x, p10.y, Ahi[tt][kt][1], Alo[tt][kt][1]);
            split_bf16x2(p01.x, p01.y, Ahi[tt][kt][2], Alo[tt][kt][2]);
            split_bf16x2(p11.x, p11.y, Ahi[tt][kt][3], Alo[tt][kt][3]);
        }
    }

    // ---- GEMM1: Y = X * Q^T (3-term), B fragment shared by both tiles ----
    float C0[8][4], C1[8][4];
    #pragma unroll
    for (int nt = 0; nt < 8; ++nt)
        #pragma unroll
        for (int e = 0; e < 4; ++e) { C0[nt][e] = 0.0f; C1[nt][e] = 0.0f; }

    #pragma unroll
    for (int nt = 0; nt < 8; ++nt) {
        #pragma unroll
        for (int kt = 0; kt < 4; ++kt) {
            uint4 bb = g_B1[(kt*8 + nt)*32 + lane];
            MMA_BF16(C0[nt], Ahi[0][kt][0], Ahi[0][kt][1], Ahi[0][kt][2], Ahi[0][kt][3], bb.x, bb.y);
            MMA_BF16(C0[nt], Alo[0][kt][0], Alo[0][kt][1], Alo[0][kt][2], Alo[0][kt][3], bb.x, bb.y);
            MMA_BF16(C0[nt], Ahi[0][kt][0], Ahi[0][kt][1], Ahi[0][kt][2], Ahi[0][kt][3], bb.z, bb.w);
            MMA_BF16(C1[nt], Ahi[1][kt][0], Ahi[1][kt][1], Ahi[1][kt][2], Ahi[1][kt][3], bb.x, bb.y);
            MMA_BF16(C1[nt], Alo[1][kt][0], Alo[1][kt][1], Alo[1][kt][2], Alo[1][kt][3], bb.x, bb.y);
            MMA_BF16(C1[nt], Ahi[1][kt][0], Ahi[1][kt][1], Ahi[1][kt][2], Ahi[1][kt][3], bb.z, bb.w);
        }
    }

    // ---- rope: rows g and g+8 share s -> same cos/sin; both tiles share too ----
    {
        const float* cr = &cs[g * XS_STRIDE];
        const float* sr = &ss[g * XS_STRIDE];
        #pragma unroll
        for (int nt = 0; nt < 4; ++nt) {
            int c = 8*nt + 2*t4;
            float2 cl = *(const float2*)(cr + c);
            float2 ch = *(const float2*)(cr + c + 32);
            float2 sl = *(const float2*)(sr + c);
            float2 sh = *(const float2*)(sr + c + 32);
            #pragma unroll
            for (int e = 0; e < 4; ++e) {
                float cle = (e & 1) ? cl.y : cl.x;
                float che = (e & 1) ? ch.y : ch.x;
                float sle = (e & 1) ? sl.y : sl.x;
                float she = (e & 1) ? sh.y : sh.x;
                float ylo0 = C0[nt][e], yhi0 = C0[nt+4][e];
                C0[nt][e]   = ylo0*cle - yhi0*sle;
                C0[nt+4][e] = yhi0*che + ylo0*she;
                float ylo1 = C1[nt][e], yhi1 = C1[nt+4][e];
                C1[nt][e]   = ylo1*cle - yhi1*sle;
                C1[nt+4][e] = yhi1*che + ylo1*she;
            }
        }
    }

    // ---- Z -> A2 fragments (reuse A register arrays) ----
    #pragma unroll
    for (int kt = 0; kt < 4; ++kt) {
        split_bf16x2(C0[2*kt][0],   C0[2*kt][1],   Ahi[0][kt][0], Alo[0][kt][0]);
        split_bf16x2(C0[2*kt][2],   C0[2*kt][3],   Ahi[0][kt][1], Alo[0][kt][1]);
        split_bf16x2(C0[2*kt+1][0], C0[2*kt+1][1], Ahi[0][kt][2], Alo[0][kt][2]);
        split_bf16x2(C0[2*kt+1][2], C0[2*kt+1][3], Ahi[0][kt][3], Alo[0][kt][3]);
        split_bf16x2(C1[2*kt][0],   C1[2*kt][1],   Ahi[1][kt][0], Alo[1][kt][0]);
        split_bf16x2(C1[2*kt][2],   C1[2*kt][3],   Ahi[1][kt][1], Alo[1][kt][1]);
        split_bf16x2(C1[2*kt+1][0], C1[2*kt+1][1], Ahi[1][kt][2], Alo[1][kt][2]);
        split_bf16x2(C1[2*kt+1][2], C1[2*kt+1][3], Ahi[1][kt][3], Alo[1][kt][3]);
    }

    // ---- GEMM2: O = Z * Q ----
    #pragma unroll
    for (int nt = 0; nt < 8; ++nt)
        #pragma unroll
        for (int e = 0; e < 4; ++e) { C0[nt][e] = 0.0f; C1[nt][e] = 0.0f; }

    #pragma unroll
    for (int nt = 0; nt < 8; ++nt) {
        #pragma unroll
        for (int kt = 0; kt < 4; ++kt) {
            uint4 bb = g_B2[(kt*8 + nt)*32 + lane];
            MMA_BF16(C0[nt], Ahi[0][kt][0], Ahi[0][kt][1], Ahi[0][kt][2], Ahi[0][kt][3], bb.x, bb.y);
            MMA_BF16(C0[nt], Alo[0][kt][0], Alo[0][kt][1], Alo[0][kt][2], Alo[0][kt][3], bb.x, bb.y);
            MMA_BF16(C0[nt], Ahi[0][kt][0], Ahi[0][kt][1], Ahi[0][kt][2], Ahi[0][kt][3], bb.z, bb.w);
            MMA_BF16(C1[nt], Ahi[1][kt][0], Ahi[1][kt][1], Ahi[1][kt][2], Ahi[1][kt][3], bb.x, bb.y);
            MMA_BF16(C1[nt], Alo[1][kt][0], Alo[1][kt][1], Alo[1][kt][2], Alo[1][kt][3], bb.x, bb.y);
            MMA_BF16(C1[nt], Ahi[1][kt][0], Ahi[1][kt][1], Ahi[1][kt][2], Ahi[1][kt][3], bb.z, bb.w);
        }
    }

    // ---- store: fragments -> smem (reuse xs), then coalesced flush ----
    __syncthreads();   // all warps done reading xs
    #pragma unroll
    for (int tt = 0; tt < 2; ++tt) {
        int tb = (warp * 2 + tt) * 16;
        float* o0 = &xs[(tb + g) * XS_STRIDE];
        float* o1 = &xs[(tb + g + 8) * XS_STRIDE];
        #pragma unroll
        for (int nt = 0; nt < 8; ++nt) {
            int c = 8*nt + 2*t4;
            float2 v0, v1;
            if (tt == 0) { v0.x = C0[nt][0]; v0.y = C0[nt][1]; v1.x = C0[nt][2]; v1.y = C0[nt][3]; }
            else         { v0.x = C1[nt][0]; v0.y = C1[nt][1]; v1.x = C1[nt][2]; v1.y = C1[nt][3]; }
            *(float2*)(o0 + c) = v0;
            *(float2*)(o1 + c) = v1;
        }
    }
    __syncthreads();

    const size_t obase = (size_t)tensor * NROWS_Q * DD;
    #pragma unroll
    for (int it = 0; it < 16; ++it) {
        int lin = it * 128 + tid;
        int rl  = lin >> 4;
        int c4  = (lin & 15) << 2;
        int h   = rl >> 3, ds = rl & 7;
        size_t gofs = obase + (((size_t)(b * 16 + h)) * SSS + s0 + ds) * DD + c4;
        *(float4*)(out + gofs) = *(const float4*)&xs[rl * XS_STRIDE + c4];
    }
}

extern "C" void kernel_launch(void* const* d_in, const int* in_sizes, int n_in,
                              void* d_out, int out_size) {
    const float* q    = (const float*)d_in[0];
    const float* k    = (const float*)d_in[1];
    const float* cosp = (const float*)d_in[2];
    const float* sinp = (const float*)d_in[3];
    const float* vs   = (const float*)d_in[4];
    float* out = (float*)d_out;

    build_q_kernel<<<1, 256>>>(vs);
    rnrope_mma_kernel<<<NROWS_T / 128, 128>>>(q, k, cosp, sinp, out);
}